// round 5
// baseline (speedup 1.0000x reference)
#include <cuda_runtime.h>
#include <cuda_fp16.h>
#include <math.h>

#define N_NODES 100000
#define N_EDGES 1600000
#define MAX_ITER 50

typedef unsigned long long u64;

// ---------------- device scratch (static, no allocs) ----------------
// F stored PAIR-INTERLEAVED fp16: for edge pair p (edges 2p,2p+1):
//   g_F[p*32 + 2*j + lane] = F_{2p+lane}[j],  j=0..14  (32 halfs = 64B per pair)
__device__ __half g_F[(size_t)N_EDGES * 16];
__device__ int    g_psrc[N_EDGES];
__device__ int    g_prow[N_EDGES];
__device__ float  g_pval[N_EDGES];
__device__ int    g_cnt[N_NODES];
__device__ int    g_cursor[N_NODES];
__device__ int    g_bsum[128];
__device__ int    g_bsumx[128];
__device__ float  g_state[N_NODES * 8];
__device__ float  g_old[N_NODES * 8];
__device__ float  g_new[N_NODES * 8];
__device__ int    g_flags[MAX_ITER + 1];
__device__ int    g_num;
__device__ u64    g_wstage[168];              // staging for paired weights

// ---------------- constant weights ----------------
__constant__ float cW1a[8 * 15];
__constant__ float cb1[15];
__constant__ float cW3[5 * 10];
__constant__ float cb3[10];
__constant__ float cW4[10 * 7];
__constant__ float cb4[7];
// paired (w,w) weights for f32x2 path:
//   [0..74]    W1b dup, index d*15+j
//   [80..154]  W2  dup, index j*5+c
//   [160..164] b2  dup
__constant__ u64 cWp[168];

__device__ __forceinline__ float tanh_fast(float x) {
    float y;
    asm("tanh.approx.f32 %0, %1;" : "=f"(y) : "f"(x));
    return y;
}
__device__ __forceinline__ u64 pack2(float lo, float hi) {
    u64 r;
    asm("mov.b64 %0, {%1, %2};" : "=l"(r) : "f"(lo), "f"(hi));
    return r;
}
__device__ __forceinline__ void unpack2(u64 v, float& lo, float& hi) {
    asm("mov.b64 {%0, %1}, %2;" : "=f"(lo), "=f"(hi) : "l"(v));
}
__device__ __forceinline__ u64 fma2(u64 a, u64 b, u64 c) {
    u64 d;
    asm("fma.rn.f32x2 %0, %1, %2, %3;" : "=l"(d) : "l"(a), "l"(b), "l"(c));
    return d;
}

// ---------------- init ----------------
__global__ void init_flags_kernel() {
    int t = threadIdx.x;
    if (t <= MAX_ITER) g_flags[t] = 0;
    if (t == 63) g_num = 0;
}

__global__ void prep_weights_kernel(const float* __restrict__ W1,
                                    const float* __restrict__ W2,
                                    const float* __restrict__ b2) {
    int t = threadIdx.x;   // 256 threads
    if (t < 75) {                           // W1b rows 8..12 of W1
        float w = W1[8 * 15 + t];           // layout d*15+j already
        g_wstage[t] = pack2(w, w);
    }
    if (t >= 128 && t < 203) {
        float w = W2[t - 128];              // layout j*5+c
        g_wstage[80 + (t - 128)] = pack2(w, w);
    }
    if (t >= 208 && t < 213) {
        float w = b2[t - 208];
        g_wstage[160 + (t - 208)] = pack2(w, w);
    }
}

__global__ __launch_bounds__(256) void init_nodes_kernel(
    const float* __restrict__ state_init,
    const float* __restrict__ old_init)
{
    int i = blockIdx.x * blockDim.x + threadIdx.x;
    bool exceed = false;
    if (i < N_NODES) {
        g_cnt[i] = 0;
        float d2 = 0.f;
        #pragma unroll
        for (int c = 0; c < 5; c++) {
            float s = state_init[i * 5 + c];
            float o = old_init[i * 5 + c];
            g_state[i * 8 + c] = s;
            g_old[i * 8 + c]   = o;
            g_new[i * 8 + c]   = 0.f;
            float d = s - o;
            d2 += d * d;
        }
        #pragma unroll
        for (int c = 5; c < 8; c++) {
            g_state[i * 8 + c] = 0.f;
            g_old[i * 8 + c]   = 0.f;
            g_new[i * 8 + c]   = 0.f;
        }
        exceed = sqrtf(d2 + 1e-11f) > 0.01f;
    }
    unsigned b = __ballot_sync(0xffffffffu, exceed);
    if ((threadIdx.x & 31) == 0 && b) atomicOr(&g_flags[0], 1);
}

// ---------------- counting sort by arc_rows ----------------
__global__ __launch_bounds__(256) void hist_kernel(const int* __restrict__ arc_rows) {
    int e = blockIdx.x * blockDim.x + threadIdx.x;
    if (e < N_EDGES) atomicAdd(&g_cnt[arc_rows[e]], 1);
}

__global__ __launch_bounds__(256) void scanA_kernel() {
    __shared__ int sh[256];
    int t = threadIdx.x, b = blockIdx.x;
    int base = b * 1024 + t * 4;
    int s = 0;
    #pragma unroll
    for (int j = 0; j < 4; j++) {
        int idx = base + j;
        if (idx < N_NODES) s += g_cnt[idx];
    }
    sh[t] = s; __syncthreads();
    for (int off = 1; off < 256; off <<= 1) {
        int v = (t >= off) ? sh[t - off] : 0;
        __syncthreads();
        sh[t] += v;
        __syncthreads();
    }
    if (t == 255) g_bsum[b] = sh[255];
}

__global__ void scanB_kernel(int nblocks) {
    if (threadIdx.x == 0) {
        int acc = 0;
        for (int b = 0; b < nblocks; b++) {
            g_bsumx[b] = acc;
            acc += g_bsum[b];
        }
    }
}

__global__ __launch_bounds__(256) void scanC_kernel() {
    __shared__ int sh[256];
    int t = threadIdx.x, b = blockIdx.x;
    int base = b * 1024 + t * 4;
    int c[4], s = 0;
    #pragma unroll
    for (int j = 0; j < 4; j++) {
        int idx = base + j;
        c[j] = (idx < N_NODES) ? g_cnt[idx] : 0;
        s += c[j];
    }
    sh[t] = s; __syncthreads();
    for (int off = 1; off < 256; off <<= 1) {
        int v = (t >= off) ? sh[t - off] : 0;
        __syncthreads();
        sh[t] += v;
        __syncthreads();
    }
    int excl = g_bsumx[b] + sh[t] - s;
    #pragma unroll
    for (int j = 0; j < 4; j++) {
        int idx = base + j;
        if (idx < N_NODES) g_cursor[idx] = excl;
        excl += c[j];
    }
}

// scatter edges into sorted order + compute F (pair-interleaved fp16)
__global__ __launch_bounds__(256) void scatter_precompute_kernel(
    const float* __restrict__ edge_feat,
    const int*   __restrict__ edge_src,
    const int*   __restrict__ arc_rows,
    const float* __restrict__ arc_vals)
{
    int e = blockIdx.x * blockDim.x + threadIdx.x;
    if (e >= N_EDGES) return;
    int row = arc_rows[e];
    int pos = atomicAdd(&g_cursor[row], 1);
    g_psrc[pos] = edge_src[e];
    g_prow[pos] = row;
    g_pval[pos] = arc_vals[e];

    const float4* efp = (const float4*)(edge_feat + (size_t)e * 8);
    float4 a0 = efp[0], a1 = efp[1];
    float ef[8] = {a0.x, a0.y, a0.z, a0.w, a1.x, a1.y, a1.z, a1.w};
    size_t pair = (size_t)(pos >> 1) * 32 + (pos & 1);
    #pragma unroll
    for (int j = 0; j < 15; j++) {
        float acc = cb1[j];
        #pragma unroll
        for (int d = 0; d < 8; d++) acc += ef[d] * cW1a[d * 15 + j];
        g_F[pair + 2 * j] = __float2half_rn(acc);
    }
    g_F[pair + 30] = __float2half_rn(0.f);   // pad
}

// ---------------- per-iteration kernels ----------------
// 800000 threads, each handles edges (2t, 2t+1) via packed f32x2
__global__ __launch_bounds__(256) void edge_kernel(int k)
{
    if (g_flags[k] == 0) return;
    int t = blockIdx.x * blockDim.x + threadIdx.x;   // 0..799999 exactly

    int2   src2 = ((const int2*)g_psrc)[t];
    int2   row2 = ((const int2*)g_prow)[t];
    float2 av2  = ((const float2*)g_pval)[t];

    float4 sA = *(const float4*)(g_state + src2.x * 8);
    float  a4 = g_state[src2.x * 8 + 4];
    float4 sB = *(const float4*)(g_state + src2.y * 8);
    float  b4v = g_state[src2.y * 8 + 4];
    u64 sp[5];
    sp[0] = pack2(sA.x, sB.x);
    sp[1] = pack2(sA.y, sB.y);
    sp[2] = pack2(sA.z, sB.z);
    sp[3] = pack2(sA.w, sB.w);
    sp[4] = pack2(a4, b4v);

    // F pair: 64 bytes, lanes pre-interleaved
    const float4* fp = (const float4*)(g_F + (size_t)t * 32);
    union { float4 v4[4]; __half2 h2[16]; } uf;
    uf.v4[0] = fp[0]; uf.v4[1] = fp[1]; uf.v4[2] = fp[2]; uf.v4[3] = fp[3];

    u64 acc[15];
    #pragma unroll
    for (int j = 0; j < 15; j++) {
        float2 f = __half22float2(uf.h2[j]);
        acc[j] = pack2(f.x, f.y);
    }
    #pragma unroll
    for (int d = 0; d < 5; d++) {
        #pragma unroll
        for (int j = 0; j < 15; j++)
            acc[j] = fma2(sp[d], cWp[d * 15 + j], acc[j]);
    }

    u64 hp[15];
    #pragma unroll
    for (int j = 0; j < 15; j++) {
        float x, y;
        unpack2(acc[j], x, y);
        hp[j] = pack2(tanh_fast(x), tanh_fast(y));
    }

    u64 a2[5];
    #pragma unroll
    for (int c = 0; c < 5; c++) a2[c] = cWp[160 + c];
    #pragma unroll
    for (int j = 0; j < 15; j++) {
        #pragma unroll
        for (int c = 0; c < 5; c++)
            a2[c] = fma2(hp[j], cWp[80 + j * 5 + c], a2[c]);
    }

    float v0[5], v1[5];
    #pragma unroll
    for (int c = 0; c < 5; c++) {
        float x, y;
        unpack2(a2[c], x, y);
        v0[c] = tanh_fast(x) * av2.x;
        v1[c] = tanh_fast(y) * av2.y;
    }

    // pair merge: both edges same row -> fold; else orphan-atomic the lo edge
    int  key = row2.y;
    bool split = (row2.x != row2.y);
    float val[5];
    #pragma unroll
    for (int c = 0; c < 5; c++) val[c] = split ? v1[c] : (v0[c] + v1[c]);
    if (split) {
        #pragma unroll
        for (int c = 0; c < 5; c++)
            atomicAdd(&g_new[row2.x * 8 + c], v0[c]);
    }

    // warp-segmented suffix reduction over merged items (keys non-decreasing)
    const unsigned FULL = 0xffffffffu;
    int lane = threadIdx.x & 31;
    int pkey = __shfl_up_sync(FULL, key, 1);
    bool head = (lane == 0) || (pkey != key);

    #pragma unroll
    for (int off = 1; off < 32; off <<= 1) {
        int k2 = __shfl_down_sync(FULL, key, off);
        bool ok = (lane + off < 32) && (k2 == key);
        #pragma unroll
        for (int c = 0; c < 5; c++) {
            float s = __shfl_down_sync(FULL, val[c], off);
            if (ok) val[c] += s;
        }
    }

    if (head) {
        #pragma unroll
        for (int c = 0; c < 5; c++)
            atomicAdd(&g_new[key * 8 + c], val[c]);
    }
}

__global__ __launch_bounds__(256) void update_kernel(int k) {
    if (g_flags[k] == 0) return;
    int i = blockIdx.x * blockDim.x + threadIdx.x;
    bool exceed = false;
    if (i < N_NODES) {
        float4* np = (float4*)(g_new + i * 8);
        float4* sp = (float4*)(g_state + i * 8);
        float4* op = (float4*)(g_old + i * 8);
        float4 n0 = np[0], n1 = np[1];
        float4 s0 = sp[0], s1 = sp[1];
        op[0] = s0; op[1] = s1;
        sp[0] = n0; sp[1] = n1;
        np[0] = make_float4(0.f, 0.f, 0.f, 0.f);
        np[1] = make_float4(0.f, 0.f, 0.f, 0.f);
        float dx = n0.x - s0.x, dy = n0.y - s0.y, dz = n0.z - s0.z,
              dw = n0.w - s0.w, d4 = n1.x - s1.x;
        float d2 = dx * dx + dy * dy + dz * dz + dw * dw + d4 * d4;
        exceed = sqrtf(d2 + 1e-11f) > 0.01f;
        if (i == 0) g_num += 1;
    }
    unsigned b = __ballot_sync(0xffffffffu, exceed);
    if ((threadIdx.x & 31) == 0 && b) atomicOr(&g_flags[k + 1], 1);
}

__global__ __launch_bounds__(256) void output_kernel(float* __restrict__ out, int out_size) {
    int i = blockIdx.x * blockDim.x + threadIdx.x;
    if (i >= N_NODES) return;

    float s[5];
    #pragma unroll
    for (int c = 0; c < 5; c++) s[c] = g_state[i * 8 + c];

    float o1[10];
    #pragma unroll
    for (int j = 0; j < 10; j++) {
        float a = cb3[j];
        #pragma unroll
        for (int c = 0; c < 5; c++) a += s[c] * cW3[c * 10 + j];
        o1[j] = tanh_fast(a);
    }

    float l[7];
    #pragma unroll
    for (int c = 0; c < 7; c++) {
        float a = cb4[c];
        #pragma unroll
        for (int j = 0; j < 10; j++) a += o1[j] * cW4[j * 7 + c];
        l[c] = a;
    }

    float m = l[0];
    #pragma unroll
    for (int c = 1; c < 7; c++) m = fmaxf(m, l[c]);
    float ex[7];
    float sum = 0.f;
    #pragma unroll
    for (int c = 0; c < 7; c++) { ex[c] = __expf(l[c] - m); sum += ex[c]; }
    float inv = 1.0f / sum;
    #pragma unroll
    for (int c = 0; c < 7; c++) out[i * 7 + c] = ex[c] * inv;

    if (i == 0 && out_size > N_NODES * 7) {
        out[N_NODES * 7] = (float)g_num;
    }
}

// ---------------- launcher ----------------
extern "C" void kernel_launch(void* const* d_in, const int* in_sizes, int n_in,
                              void* d_out, int out_size)
{
    const float* edge_feat  = (const float*)d_in[0];
    const int*   edge_src   = (const int*)  d_in[1];
    const int*   arc_rows   = (const int*)  d_in[2];
    const float* arc_vals   = (const float*)d_in[3];
    const float* state_init = (const float*)d_in[4];
    const float* old_init   = (const float*)d_in[5];
    const float* W1 = (const float*)d_in[6];
    const float* b1 = (const float*)d_in[7];
    const float* W2 = (const float*)d_in[8];
    const float* b2 = (const float*)d_in[9];
    const float* W3 = (const float*)d_in[10];
    const float* b3 = (const float*)d_in[11];
    const float* W4 = (const float*)d_in[12];
    const float* b4 = (const float*)d_in[13];

    cudaMemcpyToSymbolAsync(cW1a, W1, 8 * 15 * sizeof(float), 0, cudaMemcpyDeviceToDevice, 0);
    cudaMemcpyToSymbolAsync(cb1,  b1, 15 * sizeof(float),     0, cudaMemcpyDeviceToDevice, 0);
    cudaMemcpyToSymbolAsync(cW3,  W3, 5 * 10 * sizeof(float), 0, cudaMemcpyDeviceToDevice, 0);
    cudaMemcpyToSymbolAsync(cb3,  b3, 10 * sizeof(float),     0, cudaMemcpyDeviceToDevice, 0);
    cudaMemcpyToSymbolAsync(cW4,  W4, 10 * 7 * sizeof(float), 0, cudaMemcpyDeviceToDevice, 0);
    cudaMemcpyToSymbolAsync(cb4,  b4, 7 * sizeof(float),      0, cudaMemcpyDeviceToDevice, 0);

    // paired (w,w) weights: device staging kernel -> constant
    prep_weights_kernel<<<1, 256>>>(W1, W2, b2);
    void* stage_addr = nullptr;
    cudaGetSymbolAddress(&stage_addr, g_wstage);
    cudaMemcpyToSymbolAsync(cWp, stage_addr, 168 * sizeof(u64), 0, cudaMemcpyDeviceToDevice, 0);

    const int NODE_BLOCKS = (N_NODES + 255) / 256;
    const int EDGE_BLOCKS = (N_EDGES + 255) / 256;      // 6250
    const int PAIR_BLOCKS = (N_EDGES / 2 + 255) / 256;  // 3125
    const int SCAN_BLOCKS = (N_NODES + 1023) / 1024;    // 98

    init_flags_kernel<<<1, 64>>>();
    init_nodes_kernel<<<NODE_BLOCKS, 256>>>(state_init, old_init);

    hist_kernel<<<EDGE_BLOCKS, 256>>>(arc_rows);
    scanA_kernel<<<SCAN_BLOCKS, 256>>>();
    scanB_kernel<<<1, 32>>>(SCAN_BLOCKS);
    scanC_kernel<<<SCAN_BLOCKS, 256>>>();
    scatter_precompute_kernel<<<EDGE_BLOCKS, 256>>>(edge_feat, edge_src, arc_rows, arc_vals);

    for (int k = 0; k < MAX_ITER; k++) {
        edge_kernel<<<PAIR_BLOCKS, 256>>>(k);
        update_kernel<<<NODE_BLOCKS, 256>>>(k);
    }

    output_kernel<<<NODE_BLOCKS, 256>>>((float*)d_out, out_size);
}

// round 6
// speedup vs baseline: 1.0909x; 1.0909x over previous
#include <cuda_runtime.h>
#include <cuda_fp16.h>
#include <math.h>

#define N_NODES 100000
#define N_EDGES 1600000
#define MAX_ITER 50

// ---------------- device scratch (static, no allocs) ----------------
__device__ __half g_F[(size_t)N_EDGES * 16];  // fp16 F sorted order, 16 halfs (32B)/edge
__device__ __half g_T[N_NODES * 16];          // fp16 per-node state@W1b, 16 halfs/node
__device__ int    g_psrc[N_EDGES];
__device__ int    g_prow[N_EDGES];
__device__ float  g_pval[N_EDGES];
__device__ int    g_cnt[N_NODES];
__device__ int    g_cursor[N_NODES];
__device__ int    g_bsum[128];
__device__ int    g_bsumx[128];
__device__ float  g_state[N_NODES * 8];
__device__ float  g_old[N_NODES * 8];
__device__ float  g_new[N_NODES * 8];
__device__ int    g_flags[MAX_ITER + 1];
__device__ int    g_num;

// ---------------- constant weights ----------------
__constant__ float cW1a[8 * 15];
__constant__ float cW1b[5 * 15];
__constant__ float cb1[15];
__constant__ float cW2[15 * 5];
__constant__ float cb2[5];
__constant__ float cW3[5 * 10];
__constant__ float cb3[10];
__constant__ float cW4[10 * 7];
__constant__ float cb4[7];

__device__ __forceinline__ float tanh_fast(float x) {
    float y;
    asm("tanh.approx.f32 %0, %1;" : "=f"(y) : "f"(x));
    return y;
}
__device__ __forceinline__ unsigned tanh2_fast(unsigned h2) {
    unsigned r;
    asm("tanh.approx.f16x2 %0, %1;" : "=r"(r) : "r"(h2));
    return r;
}

// compute T row (15 fp16 + pad) from 5 fp32 state values, store as 2x float4
__device__ __forceinline__ void store_T(int node, const float s[5]) {
    union { float4 v4[2]; __half2 h2[8]; } u;
    #pragma unroll
    for (int j = 0; j < 8; j++) {
        float lo = 0.f, hi = 0.f;
        #pragma unroll
        for (int d = 0; d < 5; d++) lo += s[d] * cW1b[d * 15 + 2 * j];
        if (2 * j + 1 < 15) {
            #pragma unroll
            for (int d = 0; d < 5; d++) hi += s[d] * cW1b[d * 15 + 2 * j + 1];
        }
        u.h2[j] = __floats2half2_rn(lo, hi);
    }
    float4* tp = (float4*)(g_T + (size_t)node * 16);
    tp[0] = u.v4[0];
    tp[1] = u.v4[1];
}

// ---------------- init ----------------
__global__ void init_flags_kernel() {
    int t = threadIdx.x;
    if (t <= MAX_ITER) g_flags[t] = 0;
    if (t == 63) g_num = 0;
}

__global__ __launch_bounds__(256) void init_nodes_kernel(
    const float* __restrict__ state_init,
    const float* __restrict__ old_init)
{
    int i = blockIdx.x * blockDim.x + threadIdx.x;
    bool exceed = false;
    if (i < N_NODES) {
        g_cnt[i] = 0;
        float s5[5];
        float d2 = 0.f;
        #pragma unroll
        for (int c = 0; c < 5; c++) {
            float s = state_init[i * 5 + c];
            float o = old_init[i * 5 + c];
            s5[c] = s;
            g_state[i * 8 + c] = s;
            g_old[i * 8 + c]   = o;
            g_new[i * 8 + c]   = 0.f;
            float d = s - o;
            d2 += d * d;
        }
        #pragma unroll
        for (int c = 5; c < 8; c++) {
            g_state[i * 8 + c] = 0.f;
            g_old[i * 8 + c]   = 0.f;
            g_new[i * 8 + c]   = 0.f;
        }
        store_T(i, s5);
        exceed = sqrtf(d2 + 1e-11f) > 0.01f;
    }
    unsigned b = __ballot_sync(0xffffffffu, exceed);
    if ((threadIdx.x & 31) == 0 && b) atomicOr(&g_flags[0], 1);
}

// ---------------- counting sort by arc_rows ----------------
__global__ __launch_bounds__(256) void hist_kernel(const int* __restrict__ arc_rows) {
    int e = blockIdx.x * blockDim.x + threadIdx.x;
    if (e < N_EDGES) atomicAdd(&g_cnt[arc_rows[e]], 1);
}

__global__ __launch_bounds__(256) void scanA_kernel() {
    __shared__ int sh[256];
    int t = threadIdx.x, b = blockIdx.x;
    int base = b * 1024 + t * 4;
    int s = 0;
    #pragma unroll
    for (int j = 0; j < 4; j++) {
        int idx = base + j;
        if (idx < N_NODES) s += g_cnt[idx];
    }
    sh[t] = s; __syncthreads();
    for (int off = 1; off < 256; off <<= 1) {
        int v = (t >= off) ? sh[t - off] : 0;
        __syncthreads();
        sh[t] += v;
        __syncthreads();
    }
    if (t == 255) g_bsum[b] = sh[255];
}

__global__ void scanB_kernel(int nblocks) {
    if (threadIdx.x == 0) {
        int acc = 0;
        for (int b = 0; b < nblocks; b++) {
            g_bsumx[b] = acc;
            acc += g_bsum[b];
        }
    }
}

__global__ __launch_bounds__(256) void scanC_kernel() {
    __shared__ int sh[256];
    int t = threadIdx.x, b = blockIdx.x;
    int base = b * 1024 + t * 4;
    int c[4], s = 0;
    #pragma unroll
    for (int j = 0; j < 4; j++) {
        int idx = base + j;
        c[j] = (idx < N_NODES) ? g_cnt[idx] : 0;
        s += c[j];
    }
    sh[t] = s; __syncthreads();
    for (int off = 1; off < 256; off <<= 1) {
        int v = (t >= off) ? sh[t - off] : 0;
        __syncthreads();
        sh[t] += v;
        __syncthreads();
    }
    int excl = g_bsumx[b] + sh[t] - s;
    #pragma unroll
    for (int j = 0; j < 4; j++) {
        int idx = base + j;
        if (idx < N_NODES) g_cursor[idx] = excl;
        excl += c[j];
    }
}

// scatter edges into sorted order + compute F (fp16, linear layout)
__global__ __launch_bounds__(256) void scatter_precompute_kernel(
    const float* __restrict__ edge_feat,
    const int*   __restrict__ edge_src,
    const int*   __restrict__ arc_rows,
    const float* __restrict__ arc_vals)
{
    int e = blockIdx.x * blockDim.x + threadIdx.x;
    if (e >= N_EDGES) return;
    int row = arc_rows[e];
    int pos = atomicAdd(&g_cursor[row], 1);
    g_psrc[pos] = edge_src[e];
    g_prow[pos] = row;
    g_pval[pos] = arc_vals[e];

    const float4* efp = (const float4*)(edge_feat + (size_t)e * 8);
    float4 a0 = efp[0], a1 = efp[1];
    float ef[8] = {a0.x, a0.y, a0.z, a0.w, a1.x, a1.y, a1.z, a1.w};
    float v[16];
    #pragma unroll
    for (int j = 0; j < 15; j++) {
        float acc = cb1[j];
        #pragma unroll
        for (int d = 0; d < 8; d++) acc += ef[d] * cW1a[d * 15 + j];
        v[j] = acc;
    }
    v[15] = 0.f;
    union { float4 v4[2]; __half2 h2[8]; } u;
    #pragma unroll
    for (int j = 0; j < 8; j++)
        u.h2[j] = __floats2half2_rn(v[2 * j], v[2 * j + 1]);
    float4* op = (float4*)(g_F + (size_t)pos * 16);
    op[0] = u.v4[0];
    op[1] = u.v4[1];
}

// ---------------- per-iteration kernels ----------------
__global__ __launch_bounds__(256) void edge_kernel(int k)
{
    if (g_flags[k] == 0) return;
    int e = blockIdx.x * blockDim.x + threadIdx.x;   // grid exactly covers N_EDGES

    int   src = g_psrc[e];
    int   row = g_prow[e];
    float av  = g_pval[e];

    // F[e] + T[src], both 16 halfs (32B)
    const float4* fp = (const float4*)(g_F + (size_t)e * 16);
    const float4* tp = (const float4*)(g_T + (size_t)src * 16);
    union UH { float4 v4[2]; __half2 h2[8]; };
    UH uf, ut;
    uf.v4[0] = fp[0]; uf.v4[1] = fp[1];
    ut.v4[0] = tp[0]; ut.v4[1] = tp[1];

    // h1 = tanh(F + T) via fp16x2
    float h1[16];
    #pragma unroll
    for (int j = 0; j < 8; j++) {
        __half2 s = __hadd2(uf.h2[j], ut.h2[j]);
        unsigned sv; memcpy(&sv, &s, 4);
        unsigned tv = tanh2_fast(sv);
        __half2 th; memcpy(&th, &tv, 4);
        float2 f = __half22float2(th);
        h1[2 * j]     = f.x;
        h1[2 * j + 1] = f.y;
    }

    // second layer fp32
    float v[5];
    #pragma unroll
    for (int c = 0; c < 5; c++) {
        float a = cb2[c];
        #pragma unroll
        for (int j = 0; j < 15; j++) a += h1[j] * cW2[j * 5 + c];
        v[c] = tanh_fast(a) * av;
    }

    // warp-segmented suffix reduction over contiguous equal-row runs
    const unsigned FULL = 0xffffffffu;
    int lane = threadIdx.x & 31;
    int prow = __shfl_up_sync(FULL, row, 1);
    bool head = (lane == 0) || (prow != row);

    #pragma unroll
    for (int off = 1; off < 32; off <<= 1) {
        int r2 = __shfl_down_sync(FULL, row, off);
        bool ok = (lane + off < 32) && (r2 == row);
        #pragma unroll
        for (int c = 0; c < 5; c++) {
            float t = __shfl_down_sync(FULL, v[c], off);
            if (ok) v[c] += t;
        }
    }

    if (head) {
        #pragma unroll
        for (int c = 0; c < 5; c++)
            atomicAdd(&g_new[row * 8 + c], v[c]);
    }
}

__global__ __launch_bounds__(256) void update_kernel(int k) {
    if (g_flags[k] == 0) return;
    int i = blockIdx.x * blockDim.x + threadIdx.x;
    bool exceed = false;
    if (i < N_NODES) {
        float4* np = (float4*)(g_new + i * 8);
        float4* sp = (float4*)(g_state + i * 8);
        float4* op = (float4*)(g_old + i * 8);
        float4 n0 = np[0], n1 = np[1];
        float4 s0 = sp[0], s1 = sp[1];
        op[0] = s0; op[1] = s1;
        sp[0] = n0; sp[1] = n1;
        np[0] = make_float4(0.f, 0.f, 0.f, 0.f);
        np[1] = make_float4(0.f, 0.f, 0.f, 0.f);
        // refresh T = new_state @ W1b (fp16)
        float s5[5] = {n0.x, n0.y, n0.z, n0.w, n1.x};
        store_T(i, s5);
        float dx = n0.x - s0.x, dy = n0.y - s0.y, dz = n0.z - s0.z,
              dw = n0.w - s0.w, d4 = n1.x - s1.x;
        float d2 = dx * dx + dy * dy + dz * dz + dw * dw + d4 * d4;
        exceed = sqrtf(d2 + 1e-11f) > 0.01f;
        if (i == 0) g_num += 1;
    }
    unsigned b = __ballot_sync(0xffffffffu, exceed);
    if ((threadIdx.x & 31) == 0 && b) atomicOr(&g_flags[k + 1], 1);
}

__global__ __launch_bounds__(256) void output_kernel(float* __restrict__ out, int out_size) {
    int i = blockIdx.x * blockDim.x + threadIdx.x;
    if (i >= N_NODES) return;

    float s[5];
    #pragma unroll
    for (int c = 0; c < 5; c++) s[c] = g_state[i * 8 + c];

    float o1[10];
    #pragma unroll
    for (int j = 0; j < 10; j++) {
        float a = cb3[j];
        #pragma unroll
        for (int c = 0; c < 5; c++) a += s[c] * cW3[c * 10 + j];
        o1[j] = tanh_fast(a);
    }

    float l[7];
    #pragma unroll
    for (int c = 0; c < 7; c++) {
        float a = cb4[c];
        #pragma unroll
        for (int j = 0; j < 10; j++) a += o1[j] * cW4[j * 7 + c];
        l[c] = a;
    }

    float m = l[0];
    #pragma unroll
    for (int c = 1; c < 7; c++) m = fmaxf(m, l[c]);
    float ex[7];
    float sum = 0.f;
    #pragma unroll
    for (int c = 0; c < 7; c++) { ex[c] = __expf(l[c] - m); sum += ex[c]; }
    float inv = 1.0f / sum;
    #pragma unroll
    for (int c = 0; c < 7; c++) out[i * 7 + c] = ex[c] * inv;

    if (i == 0 && out_size > N_NODES * 7) {
        out[N_NODES * 7] = (float)g_num;
    }
}

// ---------------- launcher ----------------
extern "C" void kernel_launch(void* const* d_in, const int* in_sizes, int n_in,
                              void* d_out, int out_size)
{
    const float* edge_feat  = (const float*)d_in[0];
    const int*   edge_src   = (const int*)  d_in[1];
    const int*   arc_rows   = (const int*)  d_in[2];
    const float* arc_vals   = (const float*)d_in[3];
    const float* state_init = (const float*)d_in[4];
    const float* old_init   = (const float*)d_in[5];
    const float* W1 = (const float*)d_in[6];
    const float* b1 = (const float*)d_in[7];
    const float* W2 = (const float*)d_in[8];
    const float* b2 = (const float*)d_in[9];
    const float* W3 = (const float*)d_in[10];
    const float* b3 = (const float*)d_in[11];
    const float* W4 = (const float*)d_in[12];
    const float* b4 = (const float*)d_in[13];

    cudaMemcpyToSymbolAsync(cW1a, W1,           8 * 15 * sizeof(float), 0, cudaMemcpyDeviceToDevice, 0);
    cudaMemcpyToSymbolAsync(cW1b, W1 + 8 * 15,  5 * 15 * sizeof(float), 0, cudaMemcpyDeviceToDevice, 0);
    cudaMemcpyToSymbolAsync(cb1,  b1,           15 * sizeof(float),     0, cudaMemcpyDeviceToDevice, 0);
    cudaMemcpyToSymbolAsync(cW2,  W2,           15 * 5 * sizeof(float), 0, cudaMemcpyDeviceToDevice, 0);
    cudaMemcpyToSymbolAsync(cb2,  b2,           5 * sizeof(float),      0, cudaMemcpyDeviceToDevice, 0);
    cudaMemcpyToSymbolAsync(cW3,  W3,           5 * 10 * sizeof(float), 0, cudaMemcpyDeviceToDevice, 0);
    cudaMemcpyToSymbolAsync(cb3,  b3,           10 * sizeof(float),     0, cudaMemcpyDeviceToDevice, 0);
    cudaMemcpyToSymbolAsync(cW4,  W4,           10 * 7 * sizeof(float), 0, cudaMemcpyDeviceToDevice, 0);
    cudaMemcpyToSymbolAsync(cb4,  b4,           7 * sizeof(float),      0, cudaMemcpyDeviceToDevice, 0);

    const int NODE_BLOCKS = (N_NODES + 255) / 256;
    const int EDGE_BLOCKS = (N_EDGES + 255) / 256;   // 6250
    const int SCAN_BLOCKS = (N_NODES + 1023) / 1024; // 98

    init_flags_kernel<<<1, 64>>>();
    init_nodes_kernel<<<NODE_BLOCKS, 256>>>(state_init, old_init);

    hist_kernel<<<EDGE_BLOCKS, 256>>>(arc_rows);
    scanA_kernel<<<SCAN_BLOCKS, 256>>>();
    scanB_kernel<<<1, 32>>>(SCAN_BLOCKS);
    scanC_kernel<<<SCAN_BLOCKS, 256>>>();
    scatter_precompute_kernel<<<EDGE_BLOCKS, 256>>>(edge_feat, edge_src, arc_rows, arc_vals);

    for (int k = 0; k < MAX_ITER; k++) {
        edge_kernel<<<EDGE_BLOCKS, 256>>>(k);
        update_kernel<<<NODE_BLOCKS, 256>>>(k);
    }

    output_kernel<<<NODE_BLOCKS, 256>>>((float*)d_out, out_size);
}